// round 9
// baseline (speedup 1.0000x reference)
#include <cuda_runtime.h>

// YOLOv1 loss — tile-streaming fusion: each CTA streams a contiguous image
// span through double-buffered smem tiles; noobj accumulated at load time,
// per-(n,g) gather served from smem (zero scattered DRAM reads).
// S=7, B=2, C=20, D=30, CELL=64, IMG=448, LAMBDA_COORD=5, LAMBDA_NOOBJ=0.5

#define D_FEAT 30
#define S_GRID 7
#define GBOX 8
#define THREADS 512
#define NBLOCKS 296            // 2 CTAs/SM * 148 SMs
#define TI 8                   // images per tile (even -> float4 alignment)
#define TILE_F4 2940           // TI*1470/4
#define TILE_FLOATS 11760      // TI*1470
#define SMEM_BYTES (2 * TILE_FLOATS * 4)   // 94080 B, double buffer

__global__ void init_out(float* out) { out[0] = 0.0f; }

__device__ __forceinline__ float conf_pick(int m, float4 v) {
    // local float4 index idx, m = idx % 15:
    //   m==1 -> .x (row elem 4)   m==2 -> .y (elem 9)
    //   m==8 -> .z (elem 4)       m==9 -> .w (elem 9)
    return (m == 1) ? v.x : (m == 2) ? v.y : (m == 8) ? v.z : (m == 9) ? v.w : 0.0f;
}

__global__ void __launch_bounds__(THREADS, 2) yolo_loss_kernel(
    const float* __restrict__ feat,
    const float* __restrict__ bboxes,
    const int*   __restrict__ labels,
    float* __restrict__ out,
    int n_pairs)   // N/2
{
    extern __shared__ float buf[];   // [2][TILE_FLOATS]

    const float CELL = 64.0f;
    const float INV_CELL = 1.0f / 64.0f;
    const float IMG = 448.0f;
    const float INV_IMG = 1.0f / 448.0f;

    const int tid = threadIdx.x;
    const int bid = blockIdx.x;

    // balanced contiguous split in image PAIRS (keeps float4 alignment)
    const int p0 = (int)(((long long)bid       * n_pairs) / NBLOCKS);
    const int p1 = (int)(((long long)(bid + 1) * n_pairs) / NBLOCKS);
    const int img0  = 2 * p0;
    const int n_img = 2 * (p1 - p0);
    const int nt = (n_img + TI - 1) / TI;

    const int tmod = tid % 15;       // 512 % 15 == 2 -> per-k offsets {0,2,4,6,8,10}

    float acc = 0.0f;

    // ---------------- prologue: load tile 0 ----------------
    {
        const int ti_img = min(TI, n_img);
        const int nf4 = ti_img * (1470 / 2) / 2;           // ti_img*1470/4 (ti_img even)
        const float4* src = (const float4*)feat + ((size_t)img0 * 1470) / 4;
        #pragma unroll
        for (int k = 0; k < 6; k++) {
            const int idx = tid + k * THREADS;
            float4 v = make_float4(0.f, 0.f, 0.f, 0.f);
            if (idx < nf4) v = __ldg(src + idx);
            int m = tmod + (2 * k); if (m >= 15) m -= 15;
            const float c = conf_pick(m, v);
            acc = fmaf(0.5f * c, c, acc);
            if (idx < nf4) *(float4*)(buf + 4 * idx) = v;
        }
    }
    __syncthreads();

    // ---------------- main tile loop ----------------
    for (int t = 0; t < nt; t++) {
        // (a) issue next tile's loads first (keeps DRAM pipe full)
        float4 v[6];
        int nf4n = 0;
        const bool has = (t + 1 < nt);
        if (has) {
            const int ti_img_n = min(TI, n_img - (t + 1) * TI);
            nf4n = ti_img_n * (1470 / 2) / 2;
            const float4* src = (const float4*)feat
                              + ((size_t)(img0 + (t + 1) * TI) * 1470) / 4;
            #pragma unroll
            for (int k = 0; k < 6; k++) {
                const int idx = tid + k * THREADS;
                v[k] = make_float4(0.f, 0.f, 0.f, 0.f);
                if (idx < nf4n) v[k] = __ldg(src + idx);
            }
        }

        // (b) gather terms for current tile's boxes (from smem), overlaps (a)
        {
            const int ti_img = min(TI, n_img - t * TI);
            const float* cur = buf + (t & 1) * TILE_FLOATS;
            if (tid < ti_img * GBOX) {
                const int img_l = tid >> 3;
                const int g = tid & 7;
                const int img = img0 + t * TI + img_l;
                const int i = img * GBOX + g;

                const float4 bb = __ldg((const float4*)(bboxes + (size_t)i * 4));
                const float x1 = bb.x, y1 = bb.y, x2 = bb.z, y2 = bb.w;

                const float cx = 0.5f * (x1 + x2);
                const float cy = 0.5f * (y1 + y2);
                const float gw = x2 - x1;
                const float gh = y2 - y1;

                int col = (int)floorf(cx * INV_CELL);
                int row = (int)floorf(cy * INV_CELL);
                col = min(S_GRID - 1, max(0, col));
                row = min(S_GRID - 1, max(0, row));

                const float2* cell2 = (const float2*)
                    (cur + (img_l * (S_GRID * S_GRID) + row * S_GRID + col) * D_FEAT);

                const float2 q0 = cell2[0];
                const float2 q1 = cell2[1];
                const float2 q2 = cell2[2];
                const float2 q3 = cell2[3];
                const float2 q4 = cell2[4];
                const float pxs[2] = {q0.x, q2.y}, pys[2] = {q0.y, q3.x};
                const float pws[2] = {q1.x, q3.y}, phs[2] = {q1.y, q4.x};
                const float pcs[2] = {q2.x, q4.y};

                const float gx0 = (float)col * CELL;
                const float gy0 = (float)row * CELL;
                const float tx = cx * INV_CELL - (float)col;
                const float ty = cy * INV_CELL - (float)row;
                const float stw = sqrtf(gw * INV_IMG);
                const float sth = sqrtf(gh * INV_IMG);
                const float a2 = fmaxf(gw, 0.0f) * fmaxf(gh, 0.0f);

                float iou[2];
                #pragma unroll
                for (int b = 0; b < 2; b++) {
                    const float pcx = gx0 + pxs[b] * CELL;
                    const float pcy = gy0 + pys[b] * CELL;
                    const float pwa = pws[b] * IMG;
                    const float pha = phs[b] * IMG;
                    const float bx1 = pcx - 0.5f * pwa;
                    const float by1 = pcy - 0.5f * pha;
                    const float bx2 = pcx + 0.5f * pwa;
                    const float by2 = pcy + 0.5f * pha;

                    const float ix1 = fmaxf(bx1, x1);
                    const float iy1 = fmaxf(by1, y1);
                    const float ix2 = fminf(bx2, x2);
                    const float iy2 = fminf(by2, y2);
                    const float inter = fmaxf(ix2 - ix1, 0.0f) * fmaxf(iy2 - iy1, 0.0f);
                    const float a1 = fmaxf(bx2 - bx1, 0.0f) * fmaxf(by2 - by1, 0.0f);
                    iou[b] = inter / (a1 + a2 - inter + 1e-6f);
                }

                const int bi = (iou[1] > iou[0]) ? 1 : 0;   // first wins ties

                const float dpx = pxs[bi] - tx;
                const float dpy = pys[bi] - ty;
                const float dsw = sqrtf(fmaxf(pws[bi], 0.0f)) - stw;
                const float dsh = sqrtf(fmaxf(phs[bi], 0.0f)) - sth;
                acc += 5.0f * (dpx * dpx + dpy * dpy + dsw * dsw + dsh * dsh);

                const float dc = pcs[bi] - iou[bi];
                acc = fmaf(dc, dc, acc);
                acc = fmaf(-0.5f * pcs[bi], pcs[bi], acc);  // noobj correction

                const int lab = __ldg(labels + i);
                float cls = 1.0f;
                float labv = 0.0f;
                #pragma unroll
                for (int k = 0; k < 10; k++) {
                    const float2 w = cell2[5 + k];
                    cls = fmaf(w.x, w.x, cls);
                    cls = fmaf(w.y, w.y, cls);
                    const int c0 = 2 * k;
                    if (lab == c0)     labv = w.x;
                    if (lab == c0 + 1) labv = w.y;
                }
                acc += cls - 2.0f * labv;
            }
        }

        // (c) noobj on next tile's data + store to the other buffer
        if (has) {
            float* nxt = buf + ((t + 1) & 1) * TILE_FLOATS;
            #pragma unroll
            for (int k = 0; k < 6; k++) {
                const int idx = tid + k * THREADS;
                int m = tmod + (2 * k); if (m >= 15) m -= 15;
                const float c = conf_pick(m, v[k]);
                acc = fmaf(0.5f * c, c, acc);
                if (idx < nf4n) *(float4*)(nxt + 4 * idx) = v[k];
            }
        }
        __syncthreads();
    }

    // ---------------- block reduction, one atomicAdd ----------------
    __shared__ float red[16];
    const int lane = tid & 31;
    const int wid = tid >> 5;
    #pragma unroll
    for (int off = 16; off > 0; off >>= 1)
        acc += __shfl_down_sync(0xFFFFFFFFu, acc, off);
    if (lane == 0) red[wid] = acc;
    __syncthreads();
    if (wid == 0) {
        float s = (lane < (THREADS >> 5)) ? red[lane] : 0.0f;
        #pragma unroll
        for (int off = 8; off > 0; off >>= 1)
            s += __shfl_down_sync(0xFFFFFFFFu, s, off);
        if (lane == 0) atomicAdd(out, s);
    }
}

extern "C" void kernel_launch(void* const* d_in, const int* in_sizes, int n_in,
                              void* d_out, int out_size) {
    const float* feat   = (const float*)d_in[0];
    const float* bboxes = (const float*)d_in[1];
    const int*   labels = (const int*)d_in[2];
    float* out = (float*)d_out;

    const int total = in_sizes[0];                       // N * 1470
    const int N = total / (S_GRID * S_GRID * D_FEAT);    // 16384
    const int n_pairs = N / 2;

    static bool attr_set = false;   // idempotent config (same every call)
    cudaFuncSetAttribute(yolo_loss_kernel,
                         cudaFuncAttributeMaxDynamicSharedMemorySize, SMEM_BYTES);
    (void)attr_set;

    init_out<<<1, 1>>>(out);
    yolo_loss_kernel<<<NBLOCKS, THREADS, SMEM_BYTES>>>(feat, bboxes, labels, out, n_pairs);
}

// round 10
// speedup vs baseline: 1.5226x; 1.5226x over previous
#include <cuda_runtime.h>

// YOLOv1 loss — single-wave role-split kernel:
//   blocks [0,135): gather role (pipelined per-(n,g) items), then tail sweep
//   blocks [135,735): main coalesced float4 sweep, 8-way batched
// S=7, B=2, C=20, D=30, CELL=64, IMG=448, LAMBDA_COORD=5, LAMBDA_NOOBJ=0.5

#define D_FEAT 30
#define S_GRID 7
#define GBOX 8
#define THREADS 256
#define GATHER_BLOCKS 135
#define SWEEP_BLOCKS 600          // 600*256 = 153600 ≡ 0 (mod 15)
#define NBLOCKS (GATHER_BLOCKS + SWEEP_BLOCKS)   // 735 = single wave @5 CTA/SM
#define GSTRIDE (GATHER_BLOCKS * THREADS)        // 34560 ≡ 0 (mod 15)
#define SSTRIDE (SWEEP_BLOCKS * THREADS)         // 153600

__device__ __forceinline__ unsigned long long mk_policy_el() {
    unsigned long long pol;
    asm("createpolicy.fractional.L2::evict_last.b64 %0, 1.0;" : "=l"(pol));
    return pol;
}
__device__ __forceinline__ float4 ldg_el_v4(const float4* p, unsigned long long pol) {
    float4 v;
    asm volatile("ld.global.nc.L2::cache_hint.v4.f32 {%0,%1,%2,%3}, [%4], %5;"
                 : "=f"(v.x), "=f"(v.y), "=f"(v.z), "=f"(v.w)
                 : "l"(p), "l"(pol));
    return v;
}
__device__ __forceinline__ float2 ldg_el_v2(const float2* p, unsigned long long pol) {
    float2 v;
    asm volatile("ld.global.nc.L2::cache_hint.v2.f32 {%0,%1}, [%2], %3;"
                 : "=f"(v.x), "=f"(v.y)
                 : "l"(p), "l"(pol));
    return v;
}

__global__ void init_out(float* out) { out[0] = 0.0f; }

// one gather item -> partial loss
__device__ __forceinline__ float gather_item(
    int i, const float4 bb,
    const float* __restrict__ feat,
    const int*   __restrict__ labels,
    unsigned long long pol)
{
    const float CELL = 64.0f;
    const float INV_CELL = 1.0f / 64.0f;
    const float IMG = 448.0f;
    const float INV_IMG = 1.0f / 448.0f;

    const int n = i >> 3;
    const float x1 = bb.x, y1 = bb.y, x2 = bb.z, y2 = bb.w;

    const float cx = 0.5f * (x1 + x2);
    const float cy = 0.5f * (y1 + y2);
    const float gw = x2 - x1;
    const float gh = y2 - y1;

    int col = (int)floorf(cx * INV_CELL);
    int row = (int)floorf(cy * INV_CELL);
    col = min(S_GRID - 1, max(0, col));
    row = min(S_GRID - 1, max(0, row));

    const float2* cell2 = (const float2*)
        (feat + ((size_t)n * (S_GRID * S_GRID) + row * S_GRID + col) * D_FEAT);

    // issue all row loads up front (max MLP within item)
    const float2 q0 = ldg_el_v2(cell2 + 0, pol);
    const float2 q1 = ldg_el_v2(cell2 + 1, pol);
    const float2 q2 = ldg_el_v2(cell2 + 2, pol);
    const float2 q3 = ldg_el_v2(cell2 + 3, pol);
    const float2 q4 = ldg_el_v2(cell2 + 4, pol);
    const int lab = __ldg(labels + i);

    const float pxs[2] = {q0.x, q2.y}, pys[2] = {q0.y, q3.x};
    const float pws[2] = {q1.x, q3.y}, phs[2] = {q1.y, q4.x};
    const float pcs[2] = {q2.x, q4.y};

    const float gx0 = (float)col * CELL;
    const float gy0 = (float)row * CELL;
    const float tx = cx * INV_CELL - (float)col;
    const float ty = cy * INV_CELL - (float)row;
    const float stw = sqrtf(gw * INV_IMG);
    const float sth = sqrtf(gh * INV_IMG);
    const float a2 = fmaxf(gw, 0.0f) * fmaxf(gh, 0.0f);

    float iou[2];
    #pragma unroll
    for (int b = 0; b < 2; b++) {
        const float pcx = gx0 + pxs[b] * CELL;
        const float pcy = gy0 + pys[b] * CELL;
        const float pwa = pws[b] * IMG;
        const float pha = phs[b] * IMG;
        const float bx1 = pcx - 0.5f * pwa;
        const float by1 = pcy - 0.5f * pha;
        const float bx2 = pcx + 0.5f * pwa;
        const float by2 = pcy + 0.5f * pha;

        const float ix1 = fmaxf(bx1, x1);
        const float iy1 = fmaxf(by1, y1);
        const float ix2 = fminf(bx2, x2);
        const float iy2 = fminf(by2, y2);
        const float inter = fmaxf(ix2 - ix1, 0.0f) * fmaxf(iy2 - iy1, 0.0f);
        const float a1 = fmaxf(bx2 - bx1, 0.0f) * fmaxf(by2 - by1, 0.0f);
        iou[b] = inter / (a1 + a2 - inter + 1e-6f);
    }

    const int bi = (iou[1] > iou[0]) ? 1 : 0;   // first wins ties

    float r = 0.0f;
    const float dpx = pxs[bi] - tx;
    const float dpy = pys[bi] - ty;
    const float dsw = sqrtf(fmaxf(pws[bi], 0.0f)) - stw;
    const float dsh = sqrtf(fmaxf(phs[bi], 0.0f)) - sth;
    r += 5.0f * (dpx * dpx + dpy * dpy + dsw * dsw + dsh * dsh);

    const float dc = pcs[bi] - iou[bi];
    r = fmaf(dc, dc, r);
    r = fmaf(-0.5f * pcs[bi], pcs[bi], r);      // noobj correction

    float cls = 1.0f;
    float labv = 0.0f;
    #pragma unroll
    for (int k = 0; k < 10; k++) {
        const float2 w = ldg_el_v2(cell2 + 5 + k, pol);
        cls = fmaf(w.x, w.x, cls);
        cls = fmaf(w.y, w.y, cls);
        const int c0 = 2 * k;
        if (lab == c0)     labv = w.x;
        if (lab == c0 + 1) labv = w.y;
    }
    return r + cls - 2.0f * labv;
}

__global__ void __launch_bounds__(THREADS, 5) yolo_loss_kernel(
    const float*  __restrict__ feat,
    const float4* __restrict__ feat4,
    const float*  __restrict__ bboxes,
    const int*    __restrict__ labels,
    float* __restrict__ out,
    int n4,       // N*1470/4
    int M)        // N*GBOX
{
    const unsigned long long pol = mk_policy_el();
    float acc = 0.0f;

    const int n4b = n4 / 8;          // tail sweep region for gather blocks
    const int n4a = n4 - n4b;        // main sweep region

    if (blockIdx.x < GATHER_BLOCKS) {
        // ============== GATHER ROLE (then tail sweep) ==============
        const int gtid = blockIdx.x * THREADS + threadIdx.x;

        // pipelined item loop with bbox prefetch
        int i = gtid;
        float4 bb = make_float4(0.f, 0.f, 0.f, 0.f);
        if (i < M) bb = __ldg((const float4*)(bboxes + (size_t)i * 4));
        while (i < M) {
            const int inext = i + GSTRIDE;
            float4 bbn = make_float4(0.f, 0.f, 0.f, 0.f);
            if (inext < M) bbn = __ldg((const float4*)(bboxes + (size_t)inext * 4));
            acc += gather_item(i, bb, feat, labels, pol);
            bb = bbn;
            i = inext;
        }

        // tail sweep over [n4a, n4), stride GSTRIDE (≡0 mod 15)
        {
            int j = n4a + gtid;
            const int m = j % 15;
            const float mx = (m == 1) ? 1.0f : 0.0f;
            const float my = (m == 2) ? 1.0f : 0.0f;
            const float mz = (m == 8) ? 1.0f : 0.0f;
            const float mw = (m == 9) ? 1.0f : 0.0f;

            for (; j + 5 * GSTRIDE < n4; j += 6 * GSTRIDE) {
                const float4 v0 = ldg_el_v4(feat4 + j, pol);
                const float4 v1 = ldg_el_v4(feat4 + j + GSTRIDE, pol);
                const float4 v2 = ldg_el_v4(feat4 + j + 2 * GSTRIDE, pol);
                const float4 v3 = ldg_el_v4(feat4 + j + 3 * GSTRIDE, pol);
                const float4 v4 = ldg_el_v4(feat4 + j + 4 * GSTRIDE, pol);
                const float4 v5 = ldg_el_v4(feat4 + j + 5 * GSTRIDE, pol);
                float c;
                c = v0.x * mx + v0.y * my + v0.z * mz + v0.w * mw; acc = fmaf(0.5f * c, c, acc);
                c = v1.x * mx + v1.y * my + v1.z * mz + v1.w * mw; acc = fmaf(0.5f * c, c, acc);
                c = v2.x * mx + v2.y * my + v2.z * mz + v2.w * mw; acc = fmaf(0.5f * c, c, acc);
                c = v3.x * mx + v3.y * my + v3.z * mz + v3.w * mw; acc = fmaf(0.5f * c, c, acc);
                c = v4.x * mx + v4.y * my + v4.z * mz + v4.w * mw; acc = fmaf(0.5f * c, c, acc);
                c = v5.x * mx + v5.y * my + v5.z * mz + v5.w * mw; acc = fmaf(0.5f * c, c, acc);
            }
            for (; j < n4; j += GSTRIDE) {
                const float4 v = ldg_el_v4(feat4 + j, pol);
                const float c = v.x * mx + v.y * my + v.z * mz + v.w * mw;
                acc = fmaf(0.5f * c, c, acc);
            }
        }
    } else {
        // ============== MAIN SWEEP ROLE over [0, n4a) ==============
        const int sid = (blockIdx.x - GATHER_BLOCKS) * THREADS + threadIdx.x;
        const int m = sid % 15;      // SSTRIDE ≡ 0 (mod 15)
        const float mx = (m == 1) ? 1.0f : 0.0f;
        const float my = (m == 2) ? 1.0f : 0.0f;
        const float mz = (m == 8) ? 1.0f : 0.0f;
        const float mw = (m == 9) ? 1.0f : 0.0f;

        int j = sid;
        for (; j + 7 * SSTRIDE < n4a; j += 8 * SSTRIDE) {
            const float4 v0 = ldg_el_v4(feat4 + j, pol);
            const float4 v1 = ldg_el_v4(feat4 + j + SSTRIDE, pol);
            const float4 v2 = ldg_el_v4(feat4 + j + 2 * SSTRIDE, pol);
            const float4 v3 = ldg_el_v4(feat4 + j + 3 * SSTRIDE, pol);
            const float4 v4 = ldg_el_v4(feat4 + j + 4 * SSTRIDE, pol);
            const float4 v5 = ldg_el_v4(feat4 + j + 5 * SSTRIDE, pol);
            const float4 v6 = ldg_el_v4(feat4 + j + 6 * SSTRIDE, pol);
            const float4 v7 = ldg_el_v4(feat4 + j + 7 * SSTRIDE, pol);
            float c;
            c = v0.x * mx + v0.y * my + v0.z * mz + v0.w * mw; acc = fmaf(0.5f * c, c, acc);
            c = v1.x * mx + v1.y * my + v1.z * mz + v1.w * mw; acc = fmaf(0.5f * c, c, acc);
            c = v2.x * mx + v2.y * my + v2.z * mz + v2.w * mw; acc = fmaf(0.5f * c, c, acc);
            c = v3.x * mx + v3.y * my + v3.z * mz + v3.w * mw; acc = fmaf(0.5f * c, c, acc);
            c = v4.x * mx + v4.y * my + v4.z * mz + v4.w * mw; acc = fmaf(0.5f * c, c, acc);
            c = v5.x * mx + v5.y * my + v5.z * mz + v5.w * mw; acc = fmaf(0.5f * c, c, acc);
            c = v6.x * mx + v6.y * my + v6.z * mz + v6.w * mw; acc = fmaf(0.5f * c, c, acc);
            c = v7.x * mx + v7.y * my + v7.z * mz + v7.w * mw; acc = fmaf(0.5f * c, c, acc);
        }
        for (; j < n4a; j += SSTRIDE) {
            const float4 v = ldg_el_v4(feat4 + j, pol);
            const float c = v.x * mx + v.y * my + v.z * mz + v.w * mw;
            acc = fmaf(0.5f * c, c, acc);
        }
    }

    // ---- Block reduction, one atomicAdd per block
    __shared__ float red[8];
    const int lane = threadIdx.x & 31;
    const int wid = threadIdx.x >> 5;
    #pragma unroll
    for (int off = 16; off > 0; off >>= 1)
        acc += __shfl_down_sync(0xFFFFFFFFu, acc, off);
    if (lane == 0) red[wid] = acc;
    __syncthreads();
    if (wid == 0) {
        float v = (lane < (THREADS >> 5)) ? red[lane] : 0.0f;
        #pragma unroll
        for (int off = 4; off > 0; off >>= 1)
            v += __shfl_down_sync(0xFFFFFFFFu, v, off);
        if (lane == 0) atomicAdd(out, v);
    }
}

extern "C" void kernel_launch(void* const* d_in, const int* in_sizes, int n_in,
                              void* d_out, int out_size) {
    const float* feat   = (const float*)d_in[0];
    const float* bboxes = (const float*)d_in[1];
    const int*   labels = (const int*)d_in[2];
    float* out = (float*)d_out;

    const int total = in_sizes[0];                       // N * 1470
    const int n4 = total / 4;
    const int N = total / (S_GRID * S_GRID * D_FEAT);    // 16384
    const int M = N * GBOX;

    init_out<<<1, 1>>>(out);
    yolo_loss_kernel<<<NBLOCKS, THREADS>>>(feat, (const float4*)feat,
                                           bboxes, labels, out, n4, M);
}

// round 11
// speedup vs baseline: 1.6886x; 1.1090x over previous
#include <cuda_runtime.h>

// YOLOv1 loss — single-wave kernel: per-thread gather item first, then
// scattered-narrow conf sweep (4 cells/thread, 8 front-batched 4B loads).
// DRAM traffic identical to full sweep (every 128B line holds a conf value);
// L1 traffic halved vs float4 sweep. evict_last L2 policy for replay reuse.
// S=7, B=2, C=20, D=30, CELL=64, IMG=448, LAMBDA_COORD=5, LAMBDA_NOOBJ=0.5

#define D_FEAT 30
#define S_GRID 7
#define GBOX 8
#define THREADS 256
#define NBLOCKS 784            // 784*256 = 200704 threads; 802816 cells = 4x

__device__ __forceinline__ unsigned long long mk_policy_el() {
    unsigned long long pol;
    asm("createpolicy.fractional.L2::evict_last.b64 %0, 1.0;" : "=l"(pol));
    return pol;
}
__device__ __forceinline__ float ldg_el_f32(const float* p, unsigned long long pol) {
    float v;
    asm volatile("ld.global.nc.L2::cache_hint.f32 %0, [%1], %2;"
                 : "=f"(v) : "l"(p), "l"(pol));
    return v;
}
__device__ __forceinline__ float2 ldg_el_v2(const float2* p, unsigned long long pol) {
    float2 v;
    asm volatile("ld.global.nc.L2::cache_hint.v2.f32 {%0,%1}, [%2], %3;"
                 : "=f"(v.x), "=f"(v.y) : "l"(p), "l"(pol));
    return v;
}

__global__ void init_out(float* out) { out[0] = 0.0f; }

__global__ void __launch_bounds__(THREADS, 6) yolo_loss_kernel(
    const float* __restrict__ feat,
    const float* __restrict__ bboxes,
    const int*   __restrict__ labels,
    float* __restrict__ out,
    int ncells,    // N*49
    int M)         // N*GBOX
{
    const float CELL = 64.0f;
    const float INV_CELL = 1.0f / 64.0f;
    const float IMG = 448.0f;
    const float INV_IMG = 1.0f / 448.0f;

    const int tid = blockIdx.x * THREADS + threadIdx.x;
    const int T = NBLOCKS * THREADS;   // 200704
    const unsigned long long pol = mk_policy_el();

    float acc = 0.0f;

    // ================= Phase 1: gather (one (n,g) per thread, tid < M) ======
    if (tid < M) {
        const int i = tid;
        const int n = i >> 3;
        const float4 bb = __ldg((const float4*)(bboxes + (size_t)i * 4));
        const float x1 = bb.x, y1 = bb.y, x2 = bb.z, y2 = bb.w;

        const float cx = 0.5f * (x1 + x2);
        const float cy = 0.5f * (y1 + y2);
        const float gw = x2 - x1;
        const float gh = y2 - y1;

        int col = (int)floorf(cx * INV_CELL);
        int row = (int)floorf(cy * INV_CELL);
        col = min(S_GRID - 1, max(0, col));
        row = min(S_GRID - 1, max(0, row));

        const float2* cell2 = (const float2*)
            (feat + ((size_t)n * (S_GRID * S_GRID) + row * S_GRID + col) * D_FEAT);

        const float2 q0 = ldg_el_v2(cell2 + 0, pol);
        const float2 q1 = ldg_el_v2(cell2 + 1, pol);
        const float2 q2 = ldg_el_v2(cell2 + 2, pol);
        const float2 q3 = ldg_el_v2(cell2 + 3, pol);
        const float2 q4 = ldg_el_v2(cell2 + 4, pol);
        const int lab = __ldg(labels + i);

        const float pxs[2] = {q0.x, q2.y}, pys[2] = {q0.y, q3.x};
        const float pws[2] = {q1.x, q3.y}, phs[2] = {q1.y, q4.x};
        const float pcs[2] = {q2.x, q4.y};

        const float gx0 = (float)col * CELL;
        const float gy0 = (float)row * CELL;
        const float tx = cx * INV_CELL - (float)col;
        const float ty = cy * INV_CELL - (float)row;
        const float stw = sqrtf(gw * INV_IMG);
        const float sth = sqrtf(gh * INV_IMG);
        const float a2 = fmaxf(gw, 0.0f) * fmaxf(gh, 0.0f);

        float iou[2];
        #pragma unroll
        for (int b = 0; b < 2; b++) {
            const float pcx = gx0 + pxs[b] * CELL;
            const float pcy = gy0 + pys[b] * CELL;
            const float pwa = pws[b] * IMG;
            const float pha = phs[b] * IMG;
            const float bx1 = pcx - 0.5f * pwa;
            const float by1 = pcy - 0.5f * pha;
            const float bx2 = pcx + 0.5f * pwa;
            const float by2 = pcy + 0.5f * pha;

            const float ix1 = fmaxf(bx1, x1);
            const float iy1 = fmaxf(by1, y1);
            const float ix2 = fminf(bx2, x2);
            const float iy2 = fminf(by2, y2);
            const float inter = fmaxf(ix2 - ix1, 0.0f) * fmaxf(iy2 - iy1, 0.0f);
            const float a1 = fmaxf(bx2 - bx1, 0.0f) * fmaxf(by2 - by1, 0.0f);
            iou[b] = inter / (a1 + a2 - inter + 1e-6f);
        }

        const int bi = (iou[1] > iou[0]) ? 1 : 0;   // first wins ties

        const float dpx = pxs[bi] - tx;
        const float dpy = pys[bi] - ty;
        const float dsw = sqrtf(fmaxf(pws[bi], 0.0f)) - stw;
        const float dsh = sqrtf(fmaxf(phs[bi], 0.0f)) - sth;
        acc += 5.0f * (dpx * dpx + dpy * dpy + dsw * dsw + dsh * dsh);

        const float dc = pcs[bi] - iou[bi];
        acc = fmaf(dc, dc, acc);
        acc = fmaf(-0.5f * pcs[bi], pcs[bi], acc);  // noobj correction

        float cls = 1.0f;
        float labv = 0.0f;
        #pragma unroll
        for (int k = 0; k < 10; k++) {
            const float2 w = ldg_el_v2(cell2 + 5 + k, pol);
            cls = fmaf(w.x, w.x, cls);
            cls = fmaf(w.y, w.y, cls);
            const int c0 = 2 * k;
            if (lab == c0)     labv = w.x;
            if (lab == c0 + 1) labv = w.y;
        }
        acc += cls - 2.0f * labv;
    }

    // ================= Phase 2: scattered-narrow conf sweep =================
    // Each thread covers cells tid + k*T (k = 0..3); loads conf0 (elem 4)
    // and conf1 (elem 9) per cell — 8 independent 4B loads, front-batched.
    for (int c = tid; c < ncells; c += 4 * T) {
        float c0[4], c1[4];
        #pragma unroll
        for (int k = 0; k < 4; k++) {
            const int cell = c + k * T;
            if (cell < ncells) {
                const float* p = feat + (size_t)cell * D_FEAT;
                c0[k] = ldg_el_f32(p + 4, pol);
                c1[k] = ldg_el_f32(p + 9, pol);
            } else {
                c0[k] = 0.0f; c1[k] = 0.0f;
            }
        }
        #pragma unroll
        for (int k = 0; k < 4; k++) {
            acc = fmaf(0.5f * c0[k], c0[k], acc);
            acc = fmaf(0.5f * c1[k], c1[k], acc);
        }
    }

    // ---- Block reduction, one atomicAdd per block
    __shared__ float red[8];
    const int lane = threadIdx.x & 31;
    const int wid = threadIdx.x >> 5;
    #pragma unroll
    for (int off = 16; off > 0; off >>= 1)
        acc += __shfl_down_sync(0xFFFFFFFFu, acc, off);
    if (lane == 0) red[wid] = acc;
    __syncthreads();
    if (wid == 0) {
        float v = (lane < (THREADS >> 5)) ? red[lane] : 0.0f;
        #pragma unroll
        for (int off = 4; off > 0; off >>= 1)
            v += __shfl_down_sync(0xFFFFFFFFu, v, off);
        if (lane == 0) atomicAdd(out, v);
    }
}

extern "C" void kernel_launch(void* const* d_in, const int* in_sizes, int n_in,
                              void* d_out, int out_size) {
    const float* feat   = (const float*)d_in[0];
    const float* bboxes = (const float*)d_in[1];
    const int*   labels = (const int*)d_in[2];
    float* out = (float*)d_out;

    const int total = in_sizes[0];                       // N * 1470
    const int N = total / (S_GRID * S_GRID * D_FEAT);    // 16384
    const int ncells = N * S_GRID * S_GRID;              // 802816
    const int M = N * GBOX;

    init_out<<<1, 1>>>(out);
    yolo_loss_kernel<<<NBLOCKS, THREADS>>>(feat, bboxes, labels, out, ncells, M);
}

// round 12
// speedup vs baseline: 1.8209x; 1.0784x over previous
#include <cuda_runtime.h>

// YOLOv1 loss — single kernel (last-block finalize), gather + scattered-narrow
// conf sweep. 401K threads (2 cells/thread, 4 front-batched 4B conf loads).
// S=7, B=2, C=20, D=30, CELL=64, IMG=448, LAMBDA_COORD=5, LAMBDA_NOOBJ=0.5

#define D_FEAT 30
#define S_GRID 7
#define GBOX 8
#define THREADS 256
#define NBLOCKS 1568           // 1568*256 = 401408 threads; 802816 cells = 2x

__device__ float        g_acc;     // zero-init; reset by last block each call
__device__ unsigned int g_count;   // zero-init; reset by last block each call

__device__ __forceinline__ unsigned long long mk_policy_el() {
    unsigned long long pol;
    asm("createpolicy.fractional.L2::evict_last.b64 %0, 1.0;" : "=l"(pol));
    return pol;
}
__device__ __forceinline__ float ldg_el_f32(const float* p, unsigned long long pol) {
    float v;
    asm volatile("ld.global.nc.L2::cache_hint.f32 %0, [%1], %2;"
                 : "=f"(v) : "l"(p), "l"(pol));
    return v;
}
__device__ __forceinline__ float2 ldg_el_v2(const float2* p, unsigned long long pol) {
    float2 v;
    asm volatile("ld.global.nc.L2::cache_hint.v2.f32 {%0,%1}, [%2], %3;"
                 : "=f"(v.x), "=f"(v.y) : "l"(p), "l"(pol));
    return v;
}

__global__ void __launch_bounds__(THREADS, 6) yolo_loss_kernel(
    const float* __restrict__ feat,
    const float* __restrict__ bboxes,
    const int*   __restrict__ labels,
    float* __restrict__ out,
    int ncells,    // N*49
    int M)         // N*GBOX
{
    const float CELL = 64.0f;
    const float INV_CELL = 1.0f / 64.0f;
    const float IMG = 448.0f;
    const float INV_IMG = 1.0f / 448.0f;

    const int tid = blockIdx.x * THREADS + threadIdx.x;
    const int T = NBLOCKS * THREADS;   // 401408
    const unsigned long long pol = mk_policy_el();

    float acc = 0.0f;

    // ================= Phase 1: gather (one (n,g) per thread, tid < M) ======
    if (tid < M) {
        const int i = tid;
        const int n = i >> 3;
        const float4 bb = __ldg((const float4*)(bboxes + (size_t)i * 4));
        const float x1 = bb.x, y1 = bb.y, x2 = bb.z, y2 = bb.w;

        const float cx = 0.5f * (x1 + x2);
        const float cy = 0.5f * (y1 + y2);
        const float gw = x2 - x1;
        const float gh = y2 - y1;

        int col = (int)floorf(cx * INV_CELL);
        int row = (int)floorf(cy * INV_CELL);
        col = min(S_GRID - 1, max(0, col));
        row = min(S_GRID - 1, max(0, row));

        const float2* cell2 = (const float2*)
            (feat + ((size_t)n * (S_GRID * S_GRID) + row * S_GRID + col) * D_FEAT);

        const float2 q0 = ldg_el_v2(cell2 + 0, pol);
        const float2 q1 = ldg_el_v2(cell2 + 1, pol);
        const float2 q2 = ldg_el_v2(cell2 + 2, pol);
        const float2 q3 = ldg_el_v2(cell2 + 3, pol);
        const float2 q4 = ldg_el_v2(cell2 + 4, pol);
        const int lab = __ldg(labels + i);

        const float pxs[2] = {q0.x, q2.y}, pys[2] = {q0.y, q3.x};
        const float pws[2] = {q1.x, q3.y}, phs[2] = {q1.y, q4.x};
        const float pcs[2] = {q2.x, q4.y};

        const float gx0 = (float)col * CELL;
        const float gy0 = (float)row * CELL;
        const float tx = cx * INV_CELL - (float)col;
        const float ty = cy * INV_CELL - (float)row;
        const float stw = sqrtf(gw * INV_IMG);
        const float sth = sqrtf(gh * INV_IMG);
        const float a2 = fmaxf(gw, 0.0f) * fmaxf(gh, 0.0f);

        float iou[2];
        #pragma unroll
        for (int b = 0; b < 2; b++) {
            const float pcx = gx0 + pxs[b] * CELL;
            const float pcy = gy0 + pys[b] * CELL;
            const float pwa = pws[b] * IMG;
            const float pha = phs[b] * IMG;
            const float bx1 = pcx - 0.5f * pwa;
            const float by1 = pcy - 0.5f * pha;
            const float bx2 = pcx + 0.5f * pwa;
            const float by2 = pcy + 0.5f * pha;

            const float ix1 = fmaxf(bx1, x1);
            const float iy1 = fmaxf(by1, y1);
            const float ix2 = fminf(bx2, x2);
            const float iy2 = fminf(by2, y2);
            const float inter = fmaxf(ix2 - ix1, 0.0f) * fmaxf(iy2 - iy1, 0.0f);
            const float a1 = fmaxf(bx2 - bx1, 0.0f) * fmaxf(by2 - by1, 0.0f);
            iou[b] = inter / (a1 + a2 - inter + 1e-6f);
        }

        const int bi = (iou[1] > iou[0]) ? 1 : 0;   // first wins ties

        const float dpx = pxs[bi] - tx;
        const float dpy = pys[bi] - ty;
        const float dsw = sqrtf(fmaxf(pws[bi], 0.0f)) - stw;
        const float dsh = sqrtf(fmaxf(phs[bi], 0.0f)) - sth;
        acc += 5.0f * (dpx * dpx + dpy * dpy + dsw * dsw + dsh * dsh);

        const float dc = pcs[bi] - iou[bi];
        acc = fmaf(dc, dc, acc);
        acc = fmaf(-0.5f * pcs[bi], pcs[bi], acc);  // noobj correction

        float cls = 1.0f;
        float labv = 0.0f;
        #pragma unroll
        for (int k = 0; k < 10; k++) {
            const float2 w = ldg_el_v2(cell2 + 5 + k, pol);
            cls = fmaf(w.x, w.x, cls);
            cls = fmaf(w.y, w.y, cls);
            const int c0 = 2 * k;
            if (lab == c0)     labv = w.x;
            if (lab == c0 + 1) labv = w.y;
        }
        acc += cls - 2.0f * labv;
    }

    // ================= Phase 2: scattered-narrow conf sweep =================
    // 2 cells/thread (tid, tid+T): 4 independent 4B loads, front-batched.
    {
        const int c0i = tid;
        const int c1i = tid + T;
        float a0 = 0.f, a1 = 0.f, b0 = 0.f, b1 = 0.f;
        if (c0i < ncells) {
            const float* p = feat + (size_t)c0i * D_FEAT;
            a0 = ldg_el_f32(p + 4, pol);
            a1 = ldg_el_f32(p + 9, pol);
        }
        if (c1i < ncells) {
            const float* p = feat + (size_t)c1i * D_FEAT;
            b0 = ldg_el_f32(p + 4, pol);
            b1 = ldg_el_f32(p + 9, pol);
        }
        acc = fmaf(0.5f * a0, a0, acc);
        acc = fmaf(0.5f * a1, a1, acc);
        acc = fmaf(0.5f * b0, b0, acc);
        acc = fmaf(0.5f * b1, b1, acc);
    }

    // ---- Block reduction ----
    __shared__ float red[8];
    const int lane = threadIdx.x & 31;
    const int wid = threadIdx.x >> 5;
    #pragma unroll
    for (int off = 16; off > 0; off >>= 1)
        acc += __shfl_down_sync(0xFFFFFFFFu, acc, off);
    if (lane == 0) red[wid] = acc;
    __syncthreads();

    // ---- Grid finalize: atomicAdd partial, last block writes out & resets ----
    __shared__ bool is_last;
    if (threadIdx.x == 0) {
        float v = 0.0f;
        #pragma unroll
        for (int k = 0; k < (THREADS >> 5); k++) v += red[k];
        atomicAdd(&g_acc, v);
        __threadfence();
        const unsigned int prev = atomicAdd(&g_count, 1u);
        is_last = (prev == (unsigned int)(NBLOCKS - 1));
    }
    __syncthreads();
    if (is_last && threadIdx.x == 0) {
        out[0] = g_acc;
        g_acc = 0.0f;        // reset for next (deterministic) call
        __threadfence();
        g_count = 0u;
    }
}

extern "C" void kernel_launch(void* const* d_in, const int* in_sizes, int n_in,
                              void* d_out, int out_size) {
    const float* feat   = (const float*)d_in[0];
    const float* bboxes = (const float*)d_in[1];
    const int*   labels = (const int*)d_in[2];
    float* out = (float*)d_out;

    const int total = in_sizes[0];                       // N * 1470
    const int N = total / (S_GRID * S_GRID * D_FEAT);    // 16384
    const int ncells = N * S_GRID * S_GRID;              // 802816
    const int M = N * GBOX;

    yolo_loss_kernel<<<NBLOCKS, THREADS>>>(feat, bboxes, labels, out, ncells, M);
}